// round 16
// baseline (speedup 1.0000x reference)
#include <cuda_runtime.h>

// CGCoupler: out[n, ro[m]] += x1[n, r1[m]] * x2[n, r2[m]] * cg[m]
//
// prep (1 CTA, 1024 thr, RANK-BASED, no serial chains): paths are path-major
//   runs (r1/r2/ro consecutive, cg equal) over dense channel dim ns=0..deg-1;
//   run starts partition [0,M) so deg = next_start - start.
//   A:  coalesced pass flags starts, unordered atomic append (fast).
//   A2: order recovery by parallel rank (pos[q] < pos[p]) -- O(P^2) broadcast
//       comparisons over 1024 threads, deterministic, no scan carry chain.
//   C:  bin by output base ro_0 (atomic counts + one block scan), then place
//       each path at stt[bin] + rank-within-bin under canonical key
//       (deg desc, r1 asc, r2 asc) -- replaces insertion sort entirely.
//   E:  per-column {start|ns<<16, eff}; eff = #paths in bin with deg > ns.
// couple (R5 exact, measured 42.9/43.3us): 16 rows per CTA in 4-row subtiles,
//   x tiles staged 4-rows-interleaved as float4 (gathers = lane-consecutive
//   LDS.128, conflict-free), KMAX=4 register-prefetch pipeline overlaps next
//   subtile's LDG with compute, per-column loop over smem-broadcast paths.

#define N_BATCH 16384
#define ROWS    16
#define RPT     4
#define NT      (ROWS / RPT)
#define TPB     320
#define PREP_T  1024
#define MAX_OUT 2048
#define P_SMEM  512
#define NSORT   512
#define KMAX    4      // prefetch covers rep_dim <= KMAX*TPB

__device__ uint4 g_paths[P_SMEM];     // binned + canonically ordered {r1,r2,cg,deg}
__device__ uint2 g_colinfo[MAX_OUT];  // {start | ns<<16, eff}

__device__ __forceinline__ int block_incl_scan(int v, int tid, int bd) {
    __shared__ int ws[32];
    int lane = tid & 31, wid = tid >> 5;
    __syncthreads();
    #pragma unroll
    for (int d = 1; d < 32; d <<= 1) {
        int t = __shfl_up_sync(0xffffffffu, v, d);
        if (lane >= d) v += t;
    }
    if (lane == 31) ws[wid] = v;
    __syncthreads();
    if (wid == 0) {
        int w = (lane < (bd >> 5)) ? ws[lane] : 0;
        #pragma unroll
        for (int d = 1; d < 32; d <<= 1) {
            int t = __shfl_up_sync(0xffffffffu, w, d);
            if (lane >= d) w += t;
        }
        ws[lane] = w;
    }
    __syncthreads();
    return v + (wid > 0 ? ws[wid - 1] : 0);
}

__global__ void prep_kernel(const void* r1v, const void* r2v, const void* rov,
                            const float* __restrict__ cg, int M, int out_dim) {
    __shared__ int   posu[NSORT];         // unordered run-start positions
    __shared__ int   sp[NSORT + 1];       // ordered run-start positions
    __shared__ uint4 praw[NSORT];         // paths in position order
    __shared__ int   pro[NSORT];
    __shared__ uint4 pbin[P_SMEM];        // binned + canonically ordered
    __shared__ int   cnt[MAX_OUT], stt[MAX_OUT];
    __shared__ int   s_is64, s_np;
    int tid = threadIdx.x, bd = blockDim.x;

    // dtype auto-detect: int64 little-endian small values -> odd words all zero
    if (tid < 32) {
        const unsigned* w = (const unsigned*)r1v;
        int nw = M < 512 ? M : 512;
        int bad = 0;
        for (int i = 1 + 2 * tid; i < nw; i += 64) bad |= (w[i] != 0u);
        unsigned any = __ballot_sync(0xffffffffu, bad != 0);
        if (tid == 0) { s_is64 = (any == 0u); s_np = 0; }
    }
    __syncthreads();
    // 32-bit low-word access (values small, little-endian): stride 2 if int64
    int sh = s_is64 ? 1 : 0;
    const int*      A1  = (const int*)r1v;
    const int*      A2  = (const int*)r2v;
    const int*      AO  = (const int*)rov;
    const unsigned* cgu = (const unsigned*)cg;
    #define IDX1(m) A1[(m) << sh]
    #define IDX2(m) A2[(m) << sh]
    #define IDXO(m) AO[(m) << sh]
    #define ISSTART(m) ((m) == 0 || \
        !(IDX1((m) - 1) + 1 == IDX1(m) && IDX2((m) - 1) + 1 == IDX2(m) && \
          IDXO((m) - 1) + 1 == IDXO(m) && cgu[(m) - 1] == cgu[m]))

    // ---- Phase A: coalesced flag + unordered append ----
    for (int m = tid; m < M; m += bd) {
        if (ISSTART(m)) {
            int k = atomicAdd(&s_np, 1);
            if (k < NSORT) posu[k] = m;
        }
    }
    __syncthreads();
    int P = s_np;
    if (P > NSORT) P = NSORT;                  // safety; expected P ~ 150
    // ---- Phase A2: order recovery by parallel rank (deterministic) ----
    for (int p = tid; p < P; p += bd) {
        int mypos = posu[p];
        int rank = 0;
        for (int q = 0; q < P; q++) rank += (posu[q] < mypos);
        sp[rank] = mypos;
    }
    if (tid == 0) sp[P] = M;
    __syncthreads();

    // ---- Phase B: materialize paths in position order ----
    for (int p = tid; p < P; p += bd) {
        int s = sp[p];
        praw[p] = make_uint4((unsigned)IDX1(s), (unsigned)IDX2(s),
                             cgu[s], (unsigned)(sp[p + 1] - s));
        pro[p] = IDXO(s);
    }
    for (int i = tid; i < out_dim; i += bd) cnt[i] = 0;
    for (int i = tid; i < P_SMEM; i += bd) pbin[i] = make_uint4(0u, 0u, 0u, 0u);
    __syncthreads();

    // ---- Phase C: bin counts, block scan, rank-based canonical placement ----
    for (int p = tid; p < P; p += bd) atomicAdd(&cnt[pro[p]], 1);
    __syncthreads();
    {
        int CH = (out_dim + bd - 1) / bd;
        int cb = tid * CH;
        int local = 0;
        for (int i = 0; i < CH; i++) { int idx = cb + i; if (idx < out_dim) local += cnt[idx]; }
        int incl = block_incl_scan(local, tid, bd);
        int run = incl - local;
        for (int i = 0; i < CH; i++) {
            int idx = cb + i;
            if (idx < out_dim) { stt[idx] = run; run += cnt[idx]; }
        }
    }
    __syncthreads();
    // place each path at stt[bin] + rank within bin under key (deg DESC, r1, r2)
    for (int p = tid; p < P; p += bd) {
        int b = pro[p];
        uint4 me = praw[p];
        int rank = 0;
        for (int q = 0; q < P; q++) {
            if (pro[q] == b) {
                uint4 o = praw[q];
                bool oFirst = (o.w > me.w) ||
                              (o.w == me.w && (o.x < me.x ||
                               (o.x == me.x && o.y < me.y)));
                rank += oFirst;
            }
        }
        pbin[stt[b] + rank] = me;
    }
    __syncthreads();

    // ---- Phase E: per-column info + coalesced write-out ----
    for (int c = tid; c < out_dim; c += bd) {
        int b = c;
        while (b >= 0 && cnt[b] == 0) b--;
        uint2 info = make_uint2(0u, 0u);
        if (b >= 0) {
            int c0 = cnt[b], s0 = stt[b], ns = c - b, eff = 0;
            while (eff < c0 && (int)pbin[s0 + eff].w > ns) eff++;
            if (eff > 0)
                info = make_uint2((unsigned)s0 | ((unsigned)ns << 16), (unsigned)eff);
        }
        g_colinfo[c] = info;
    }
    for (int i = tid; i < P_SMEM; i += bd) g_paths[i] = pbin[i];
    #undef ISSTART
    #undef IDX1
    #undef IDX2
    #undef IDXO
}

// ===== couple: R5 exact (best measured 42.9us) =====
__global__ void __launch_bounds__(TPB)
couple_kernel(const float* __restrict__ x1, const float* __restrict__ x2,
              float* __restrict__ out, int rep_dim, int out_dim) {
    extern __shared__ char smraw[];
    float4* x1s = (float4*)smraw;              // rep_dim float4 (4 rows interleaved)
    float4* x2s = x1s + rep_dim;
    uint2*  ci  = (uint2*)(x2s + rep_dim);     // out_dim
    uint4*  pts = (uint4*)(ci + ((out_dim + 1) & ~1));  // P_SMEM paths

    int tid = threadIdx.x;
    for (int i = tid; i < P_SMEM; i += TPB) pts[i] = g_paths[i];
    for (int i = tid; i < out_dim; i += TPB) ci[i] = g_colinfo[i];

    int row0 = blockIdx.x * ROWS;

    // stage tile 0 directly
    {
        const float* a0 = x1 + (size_t)row0 * rep_dim;
        const float* b0 = x2 + (size_t)row0 * rep_dim;
        for (int i = tid; i < rep_dim; i += TPB) {
            x1s[i] = make_float4(a0[i], a0[i + rep_dim], a0[i + 2 * rep_dim], a0[i + 3 * rep_dim]);
            x2s[i] = make_float4(b0[i], b0[i + rep_dim], b0[i + 2 * rep_dim], b0[i + 3 * rep_dim]);
        }
    }
    __syncthreads();

    for (int t = 0; t < NT; t++) {
        int r = row0 + t * RPT;

        // prefetch next subtile into registers (LDG in flight during compute)
        float4 pa[KMAX], pb[KMAX];
        if (t + 1 < NT) {
            const float* a0 = x1 + (size_t)(r + RPT) * rep_dim;
            const float* b0 = x2 + (size_t)(r + RPT) * rep_dim;
            #pragma unroll
            for (int k = 0; k < KMAX; k++) {
                int i = tid + k * TPB;
                if (i < rep_dim) {
                    pa[k] = make_float4(a0[i], a0[i + rep_dim], a0[i + 2 * rep_dim], a0[i + 3 * rep_dim]);
                    pb[k] = make_float4(b0[i], b0[i + rep_dim], b0[i + 2 * rep_dim], b0[i + 3 * rep_dim]);
                }
            }
        }

        // compute current subtile
        for (int o = tid; o < out_dim; o += TPB) {
            uint2 c = ci[o];
            int s = (int)(c.x & 0xffffu);
            unsigned ns = c.x >> 16;
            int ne = (int)c.y;
            float4 acc = make_float4(0.f, 0.f, 0.f, 0.f);
            #pragma unroll 2
            for (int j = 0; j < ne; j++) {
                uint4 p = pts[s + j];                // warp-uniform: broadcast
                float cgv = __uint_as_float(p.z);
                float4 A = x1s[p.x + ns];            // lane-consecutive: conflict-free
                float4 B = x2s[p.y + ns];
                acc.x = fmaf(A.x * B.x, cgv, acc.x);
                acc.y = fmaf(A.y * B.y, cgv, acc.y);
                acc.z = fmaf(A.z * B.z, cgv, acc.z);
                acc.w = fmaf(A.w * B.w, cgv, acc.w);
            }
            float* ob = out + (size_t)r * out_dim + o;
            ob[0]                   = acc.x;
            ob[(size_t)out_dim]     = acc.y;
            ob[(size_t)out_dim * 2] = acc.z;
            ob[(size_t)out_dim * 3] = acc.w;
        }
        __syncthreads();   // everyone done reading the buffer

        if (t + 1 < NT) {
            #pragma unroll
            for (int k = 0; k < KMAX; k++) {
                int i = tid + k * TPB;
                if (i < rep_dim) { x1s[i] = pa[k]; x2s[i] = pb[k]; }
            }
            __syncthreads();   // buffer ready for next subtile
        }
    }
}

extern "C" void kernel_launch(void* const* d_in, const int* in_sizes, int n_in,
                              void* d_out, int out_size) {
    const float* x1 = (const float*)d_in[0];
    const float* x2 = (const float*)d_in[1];
    const float* cg = (const float*)d_in[2];
    const void*  r1 = d_in[3];
    const void*  r2 = d_in[4];
    const void*  ro = d_in[5];
    int M = in_sizes[2];
    int rep_dim = in_sizes[0] / N_BATCH;
    int out_dim = out_size / N_BATCH;

    prep_kernel<<<1, PREP_T>>>(r1, r2, ro, cg, M, out_dim);

    size_t smem = (size_t)rep_dim * 32 + (size_t)((out_dim + 1) & ~1) * 8
                + (size_t)P_SMEM * 16;
    cudaFuncSetAttribute(couple_kernel,
                         cudaFuncAttributeMaxDynamicSharedMemorySize, 160 * 1024);
    couple_kernel<<<N_BATCH / ROWS, TPB, smem>>>(x1, x2, (float*)d_out,
                                                 rep_dim, out_dim);
}